// round 4
// baseline (speedup 1.0000x reference)
#include <cuda_runtime.h>

// Problem constants (reference: shape_data=[8,32,32], pow=1, dt=dx=dy=1)
#define NN 1024
#define NT 8
#define NX 32
#define NY 32

// 9-point stencil offsets, order: C, E, W, N, S, NE, SW, (+1,-1), (-1,+1)
__device__ __constant__ int OFF_DI[9] = {0, 0, 0, 1, -1, 1, -1, 1, -1};
__device__ __constant__ int OFF_DJ[9] = {0, 1, -1, 0, 0, 1, -1, -1, 1};
// (di+1)*3+(dj+1) -> stencil index o
__device__ __constant__ int OMAP[9] = {6, 4, 8, 2, 0, 1, 7, 3, 5};
// inverse offset: o -> o' with off[o'] = -off[o]
__device__ __constant__ int OINV[9] = {0, 2, 1, 4, 3, 6, 5, 8, 7};

// One CTA per (b, t, j): writes the j-th row of D, lower, upper blocks (3 x 4KB).
// No CTA-wide barrier: only warps overlapping the stencil band stage & compute.
// grid: x = j (0..1023), y = t (0..7), z = b
__global__ __launch_bounds__(256) void spde_prior_kernel(
    const float* __restrict__ kappa,  // [n_b,1,NN,NT]
    const float* __restrict__ mm,     // [n_b,2,NN,NT]
    const float* __restrict__ HH,     // [n_b,2,2,NN,NT]
    const float* __restrict__ tau,    // [n_b,1,NN,NT]
    float* __restrict__ out)          // [n_b,3,NT,NN,NN]
{
    const int j    = blockIdx.x;
    const int t    = blockIdx.y;
    const int b    = blockIdx.z;
    const int tid  = threadIdx.x;
    const int w    = tid >> 5;
    const int lane = tid & 31;

    // per-warp coefficient tables, time t (slot 0) and t+1 (slot 1)
    __shared__ float e[8][2][9][9];   // e[w][ts][i][o] = M[node_i, node_i + off[o]]
    __shared__ float wv[8][2][9];     // w = 1/tau^2 at each neighbor node

    const int ii = j >> 5;
    const int jj = j & 31;

    // Each thread owns 4 consecutive columns k = 4*tid .. 4*tid+3 (same grid row ki).
    const int ki  = tid >> 3;          // (4*tid)/32
    const int kjb = (tid << 2) & 31;
    const int ddi = ki - ii;

    // warp w covers grid rows [4w, 4w+3]; involved iff it intersects [ii-2, ii+2]
    const bool involved = (4 * w <= ii + 2) && (4 * w + 3 >= ii - 2);

    float vD[4] = {0.f, 0.f, 0.f, 0.f};
    float vL[4] = {0.f, 0.f, 0.f, 0.f};
    float vU[4] = {0.f, 0.f, 0.f, 0.f};

    if (involved) {
        // Stage within this warp only: lanes 0..8 -> time t, lanes 9..17 -> time t+1
        if (lane < 18) {
            const int ts = lane / 9;
            const int o9 = lane % 9;
            const int tt = t + ts;
            const int di = OFF_DI[o9], dj = OFF_DJ[o9];
            const int ni = ii + di, nj = jj + dj;
            const bool v = (tt < NT) && (ni >= 0) && (ni < NY) && (nj >= 0) && (nj < NX);
            float wq = 0.f;
            float c0 = 0.f, cE = 0.f, cW = 0.f, cN = 0.f, cS = 0.f, cx = 0.f;
            if (v) {
                const int n     = ni * NX + nj;
                const int kbase = (b * NN + n) * NT + tt;
                const float ka  = __ldg(&kappa[kbase]);
                const float ta  = __ldg(&tau[kbase]);
                const float m1  = __ldg(&mm[(b * 2 * NN + n) * NT + tt]);
                const float m2  = __ldg(&mm[((b * 2 + 1) * NN + n) * NT + tt]);
                const float h11 = __ldg(&HH[(b * 4 * NN + n) * NT + tt]);
                const float h12 = __ldg(&HH[((b * 4 + 1) * NN + n) * NT + tt]);
                const float h22 = __ldg(&HH[((b * 4 + 3) * NN + n) * NT + tt]);
                wq = 1.f / (ta * ta);                    // dt/tau^2, dt=1
                c0 = 1.f + ka * ka + 2.f * (h11 + h22);  // M center = 1 + A center
                cE = -h11 + 0.5f * m1;
                cW = -h11 - 0.5f * m1;
                cN = -h22 + 0.5f * m2;
                cS = -h22 - 0.5f * m2;
                cx = 0.5f * h12;
            }
            const float vals[9] = {c0, cE, cW, cN, cS, -cx, -cx, cx, cx};
            #pragma unroll
            for (int o = 0; o < 9; o++) {
                // entry is zero if its COLUMN node is off-grid (Dirichlet)
                const int ci = ni + OFF_DI[o], cj = nj + OFF_DJ[o];
                const bool cv = v && (ci >= 0) && (ci < NY) && (cj >= 0) && (cj < NX);
                e[w][ts][o9][o] = cv ? vals[o] : 0.f;
            }
            wv[w][ts][o9] = wq;   // 0 for off-grid neighbor -> its terms vanish
        }
        __syncwarp();

        if (ddi >= -2 && ddi <= 2) {
            #pragma unroll
            for (int c = 0; c < 4; c++) {
                const int ddj = kjb + c - jj;
                if (ddj < -2 || ddj > 2) continue;
                // D[j,k] = sum_i w_i * M[i,j] * M[i,k]
                float sum = 0.f;
                #pragma unroll
                for (int o = 0; o < 9; o++) {
                    const int d2i = ddi - OFF_DI[o], d2j = ddj - OFF_DJ[o];
                    if (d2i < -1 || d2i > 1 || d2j < -1 || d2j > 1) continue;
                    const int o2 = OMAP[(d2i + 1) * 3 + (d2j + 1)];
                    sum += wv[w][0][o] * e[w][0][o][OINV[o]] * e[w][0][o][o2];
                }
                if (ddi == 0 && ddj == 0 && t < NT - 1)
                    sum += wv[w][1][0];               // + w_{t+1}[j] on diagonal
                vD[c] = sum;

                if (ddi >= -1 && ddi <= 1 && ddj >= -1 && ddj <= 1) {
                    const int o = OMAP[(ddi + 1) * 3 + (ddj + 1)];
                    // lower[t][j,k] = -w_t[k] * M_t[k,j]   (t==0 block is zero)
                    if (t > 0)      vL[c] = -wv[w][0][o] * e[w][0][o][OINV[o]];
                    // upper[t][j,k] = -w_{t+1}[j] * M_{t+1}[j,k]  (t==NT-1 is zero)
                    if (t < NT - 1) vU[c] = -wv[w][1][0] * e[w][1][0][o];
                }
            }
        }
    }

    // coalesced float4 stores, 3 rows (D, lower, upper)
    const size_t blk = (size_t)NT * NN * NN;
    float* base = out + ((size_t)b * 3 * NT + t) * (size_t)NN * NN + (size_t)j * NN;
    ((float4*)base)[tid]             = make_float4(vD[0], vD[1], vD[2], vD[3]);
    ((float4*)(base + blk))[tid]     = make_float4(vL[0], vL[1], vL[2], vL[3]);
    ((float4*)(base + 2 * blk))[tid] = make_float4(vU[0], vU[1], vU[2], vU[3]);
}

extern "C" void kernel_launch(void* const* d_in, const int* in_sizes, int n_in,
                              void* d_out, int out_size) {
    const float* kappa = (const float*)d_in[0];
    const float* mm    = (const float*)d_in[1];
    const float* HH    = (const float*)d_in[2];
    const float* tau   = (const float*)d_in[3];
    float* out         = (float*)d_out;

    const int n_b = in_sizes[0] / (NN * NT);   // kappa is [n_b,1,NN,NT]
    dim3 grid(NN, NT, n_b);
    spde_prior_kernel<<<grid, 256>>>(kappa, mm, HH, tau, out);
}

// round 5
// speedup vs baseline: 1.2905x; 1.2905x over previous
#include <cuda_runtime.h>

// Problem constants (reference: shape_data=[8,32,32], pow=1, dt=dx=dy=1)
#define NN 1024
#define NT 8
#define NX 32
#define NY 32

// One CTA per (b, t, j0..j0+3): writes 4 rows of each of D, lower, upper (12 x 4KB).
// grid: x = j/4 (0..255), y = t (0..7), z = b
__global__ __launch_bounds__(256) void spde_prior_kernel(
    const float* __restrict__ kappa,  // [n_b,1,NN,NT]
    const float* __restrict__ mm,     // [n_b,2,NN,NT]
    const float* __restrict__ HH,     // [n_b,2,2,NN,NT]
    const float* __restrict__ tau,    // [n_b,1,NN,NT]
    float* __restrict__ out)          // [n_b,3,NT,NN,NN]
{
    const int t   = blockIdx.y;
    const int b   = blockIdx.z;
    const int tid = threadIdx.x;
    const int j0  = blockIdx.x << 2;
    const int ii  = j0 >> 5;          // grid row of all 4 j's (4 | 32, so same row)
    const int jj0 = j0 & 31;

    // Staged M-entries for the 18 nodes (rows ii-1..ii+1, cols jj0-1..jj0+4)
    // at times t (ts=0) and t+1 (ts=1), in geometric layout:
    // se[ts][ndi][ndj][a+1][b+1] = M[node, node + (a,b)]
    __shared__ float se[2][3][6][3][3];
    __shared__ float sw[2][3][6];     // w = 1/tau^2 per node

    if (tid < 36) {
        const int ts  = tid >= 18;
        const int idx = tid - ts * 18;
        const int ndi = idx / 6;          // 0..2  -> di = ndi-1
        const int ndj = idx % 6;          // 0..5  -> dj = ndj-1
        const int tt  = t + ts;
        const int ni  = ii + ndi - 1;
        const int nj  = jj0 + ndj - 1;
        const bool v  = (tt < NT) && (ni >= 0) && (ni < NY) && (nj >= 0) && (nj < NX);
        float wq = 0.f, c0 = 0.f, cE = 0.f, cW = 0.f, cN = 0.f, cS = 0.f, cx = 0.f;
        if (v) {
            const int n     = ni * NX + nj;
            const int kbase = (b * NN + n) * NT + tt;
            const float ka  = __ldg(&kappa[kbase]);
            const float ta  = __ldg(&tau[kbase]);
            const float m1  = __ldg(&mm[(b * 2 * NN + n) * NT + tt]);
            const float m2  = __ldg(&mm[((b * 2 + 1) * NN + n) * NT + tt]);
            const float h11 = __ldg(&HH[(b * 4 * NN + n) * NT + tt]);
            const float h12 = __ldg(&HH[((b * 4 + 1) * NN + n) * NT + tt]);
            const float h22 = __ldg(&HH[((b * 4 + 3) * NN + n) * NT + tt]);
            wq = 1.f / (ta * ta);                    // dt/tau^2, dt=1
            c0 = 1.f + ka * ka + 2.f * (h11 + h22);  // M center = 1 + A center
            cE = -h11 + 0.5f * m1;
            cW = -h11 - 0.5f * m1;
            cN = -h22 + 0.5f * m2;
            cS = -h22 - 0.5f * m2;
            cx = 0.5f * h12;
        }
        // geometric entry table: [a+1][b+1], a = di of entry, b = dj
        const float ent[3][3] = { { -cx, cS,  cx },
                                  {  cW, c0,  cE },
                                  {  cx, cN, -cx } };
        #pragma unroll
        for (int a = 0; a < 3; a++)
            #pragma unroll
            for (int bb = 0; bb < 3; bb++) {
                // entry is zero if its COLUMN node is off-grid (Dirichlet)
                const int ci = ni + a - 1, cj = nj + bb - 1;
                const bool cv = v && (ci >= 0) && (ci < NY) && (cj >= 0) && (cj < NX);
                se[ts][ndi][ndj][a][bb] = cv ? ent[a][bb] : 0.f;
            }
        sw[ts][ndi][ndj] = wq;   // 0 for invalid node -> its terms vanish
    }
    __syncthreads();

    // Each thread owns 4 consecutive columns k = 4*tid .. 4*tid+3 (grid row ki).
    const int ki  = tid >> 3;
    const int kjb = (tid << 2) & 31;
    const int ddi = ki - ii;

    // thread intersects the stencil band of any of the 4 rows?
    const bool inband = (ddi >= -2) && (ddi <= 2) &&
                        (kjb <= jj0 + 5) && (kjb + 3 >= jj0 - 2);

    const size_t blk4 = (size_t)NT * NN * (NN / 4);          // block stride in float4
    float4* pD = (float4*)(out + ((size_t)b * 3 * NT + t) * (size_t)NN * NN
                               + (size_t)j0 * NN) + tid;

    #pragma unroll
    for (int jq = 0; jq < 4; jq++) {
        float4 d4 = make_float4(0.f, 0.f, 0.f, 0.f);
        float4 l4 = d4, u4 = d4;
        if (inband) {
            const int jj = jj0 + jq;
            float vD[4] = {0.f, 0.f, 0.f, 0.f};
            float vL[4] = {0.f, 0.f, 0.f, 0.f};
            float vU[4] = {0.f, 0.f, 0.f, 0.f};
            #pragma unroll
            for (int c = 0; c < 4; c++) {
                const int ddj = kjb + c - jj;
                if (ddj < -2 || ddj > 2) continue;
                // D[j,k] = sum over neighbors i of j: w_i * M[i,j] * M[i,k]
                float sum = 0.f;
                #pragma unroll
                for (int a = -1; a <= 1; a++)
                    #pragma unroll
                    for (int bo = -1; bo <= 1; bo++) {
                        const int d2i = ddi - a, d2j = ddj - bo;
                        if (d2i < -1 || d2i > 1 || d2j < -1 || d2j > 1) continue;
                        const int sj = jq + bo + 1;   // compile-time per (jq,bo)
                        sum += sw[0][a + 1][sj]
                             * se[0][a + 1][sj][1 - a][1 - bo]      // M[i,j]
                             * se[0][a + 1][sj][d2i + 1][d2j + 1];  // M[i,k]
                    }
                if (ddi == 0 && ddj == 0 && t < NT - 1)
                    sum += sw[1][1][jq + 1];          // + w_{t+1}[j] on diagonal
                vD[c] = sum;

                if (ddi >= -1 && ddi <= 1 && ddj >= -1 && ddj <= 1) {
                    // lower[t][j,k] = -w_t[k] * M_t[k,j]     (t==0 block zero)
                    if (t > 0)
                        vL[c] = -sw[0][ddi + 1][jq + ddj + 1]
                              * se[0][ddi + 1][jq + ddj + 1][1 - ddi][1 - ddj];
                    // upper[t][j,k] = -w_{t+1}[j] * M_{t+1}[j,k]  (t==NT-1 zero)
                    if (t < NT - 1)
                        vU[c] = -sw[1][1][jq + 1]
                              * se[1][1][jq + 1][ddi + 1][ddj + 1];
                }
            }
            d4 = make_float4(vD[0], vD[1], vD[2], vD[3]);
            l4 = make_float4(vL[0], vL[1], vL[2], vL[3]);
            u4 = make_float4(vU[0], vU[1], vU[2], vU[3]);
        }
        pD[jq * (NN / 4)]            = d4;
        pD[jq * (NN / 4) + blk4]     = l4;
        pD[jq * (NN / 4) + 2 * blk4] = u4;
    }
}

extern "C" void kernel_launch(void* const* d_in, const int* in_sizes, int n_in,
                              void* d_out, int out_size) {
    const float* kappa = (const float*)d_in[0];
    const float* mm    = (const float*)d_in[1];
    const float* HH    = (const float*)d_in[2];
    const float* tau   = (const float*)d_in[3];
    float* out         = (float*)d_out;

    const int n_b = in_sizes[0] / (NN * NT);   // kappa is [n_b,1,NN,NT]
    dim3 grid(NN / 4, NT, n_b);
    spde_prior_kernel<<<grid, 256>>>(kappa, mm, HH, tau, out);
}